// round 15
// baseline (speedup 1.0000x reference)
#include <cuda_runtime.h>
#include <cuda_fp16.h>
#include <stdint.h>
#include <string.h>

#define N_PTS 2048
#define M_PTS 512
#define HID   128
#define TJW   32                  // j's per warp-chunk
#define JTW   16                  // warp-chunks per i
#define NCHUNK (N_PTS * JTW)      // 32768
#define NCTA  444                 // 3 per SM
#define NWARPS (NCTA * 8)
#define PI_F  3.14159265358979323846f

// smem pitch for W2: 136 fp16 per row = 272 B -> ldmatrix conflict-free
#define PITCH_B 272

// ---- shared memory layout (bytes) ----
#define SM_W2    0                // [128][136] fp16 (W2^T) 34816
#define SM_B2W3  34816            // 128 x float2 (b2, W3) 1024
#define SM_QX    35840            // 512 x float2 = 4096
#define SM_CF4   39936            // 128 x float4 {W1r0, W1r1, b1, W1r2} 2048
#define SM_WD    41984            // 128 x float (W1r3) 512
#define SM_FLAG  42496            // is_last flag
#define SMEM_TOTAL 42560

// ---- device scratch ----
__device__ __align__(16) float g_part[NCHUNK];
__device__ unsigned int g_done;                    // zero-init; reset each run

// ---------------------------------------------------------------------------
__device__ __forceinline__ float tanh_a32(float x) {
    float r;
    asm("tanh.approx.f32 %0, %1;" : "=f"(r) : "f"(x));
    return r;
}
__device__ __forceinline__ uint32_t tanh_a16x2(uint32_t x2) {
    uint32_t r;
    asm("tanh.approx.f16x2 %0, %1;" : "=r"(r) : "r"(x2));
    return r;
}
__device__ __forceinline__ uint32_t smem_u32(const void* p) {
    uint32_t a;
    asm("{ .reg .u64 t; cvta.to.shared.u64 t, %1; cvt.u32.u64 %0, t; }"
        : "=r"(a) : "l"(p));
    return a;
}
__device__ __forceinline__ void ldsm4(uint32_t& r0, uint32_t& r1,
                                      uint32_t& r2, uint32_t& r3, uint32_t addr) {
    asm volatile("ldmatrix.sync.aligned.m8n8.x4.shared.b16 {%0,%1,%2,%3}, [%4];"
                 : "=r"(r0), "=r"(r1), "=r"(r2), "=r"(r3) : "r"(addr));
}
__device__ __forceinline__ void mma_f16(float* d, const uint32_t* a,
                                        const uint32_t* b) {
    asm volatile(
        "mma.sync.aligned.m16n8k16.row.col.f32.f16.f16.f32 "
        "{%0,%1,%2,%3}, {%4,%5,%6,%7}, {%8,%9}, {%0,%1,%2,%3};"
        : "+f"(d[0]), "+f"(d[1]), "+f"(d[2]), "+f"(d[3])
        : "r"(a[0]), "r"(a[1]), "r"(a[2]), "r"(a[3]), "r"(b[0]), "r"(b[1]));
}
__device__ __forceinline__ uint32_t h2u(__half2 h) {
    uint32_t u; memcpy(&u, &h, 4); return u;
}

// ---------------------------------------------------------------------------
// Single persistent kernel, warp-autonomous chunks, m-SPLIT GEMM:
// the 32-j chunk is processed as two m16 halves so A-fragments need only
// 32 registers -> 3 CTAs/SM (24 warps). Per half: compute A frags directly
// in mma layout (no smem), then nb-loop (B via ldmatrix from static W2),
// fused tanh.approx.f32 epilogue into p0..p3 (rows r, r+8, r+16, r+24).
// Tail: last CTA (atomic ticket) computes Y and sums g_part -> out.
// ---------------------------------------------------------------------------
__global__ void __launch_bounds__(256, 3) modnet_mma_kernel(
        const float* __restrict__ inp,
        const float* __restrict__ qx,
        const float* __restrict__ ep,
        const float* __restrict__ W1,
        const float* __restrict__ b1,
        const float* __restrict__ W2,
        const float* __restrict__ b2,
        const float* __restrict__ W3,
        const float* __restrict__ b3,
        float* __restrict__ out) {
    extern __shared__ char smem[];
    const uint32_t sb = smem_u32(smem);
    const int tid = threadIdx.x, lane = tid & 31, wid = tid >> 5;

    // ---- prologue: W2^T (fp16), b2/W3, W1 coef pack, qx into smem ----
    for (int e = tid; e < HID * 64; e += 256) {
        int n = e & 127, cp = e >> 7, c = cp * 2;
        __half2 h = __floats2half2_rn(W2[c * HID + n], W2[(c + 1) * HID + n]);
        *(uint32_t*)(smem + SM_W2 + (uint32_t)(n * PITCH_B + cp * 4)) = h2u(h);
    }
    if (tid < HID) {
        float2 v; v.x = b2[tid]; v.y = W3[tid];
        *(float2*)(smem + SM_B2W3 + tid * 8) = v;
        float4 cf;
        cf.x = W1[tid];            // row 0 (x0 weight)
        cf.y = W1[128 + tid];      // row 1 (x1 weight)
        cf.z = b1[tid];
        cf.w = W1[256 + tid];      // row 2 (qx weight)
        *(float4*)(smem + SM_CF4 + tid * 16) = cf;
        *(float*)(smem + SM_WD + tid * 4) = W1[384 + tid];  // row 3 (qy weight)
    }
    for (int e = tid; e < M_PTS * 2; e += 256)
        ((float*)(smem + SM_QX))[e] = qx[e];
    __syncthreads();

    const float2* bw   = (const float2*)(smem + SM_B2W3);
    const float*  qxs  = (const float*)(smem + SM_QX);
    const float4* cf4s = (const float4*)(smem + SM_CF4);
    const float*  wds  = (const float*)(smem + SM_WD);
    const float epi = ep[0] * PI_F;
    const int r  = lane >> 2;            // fragment row group
    const int cq = 2 * (lane & 3);       // fragment col base within k-step

    const uint32_t bAddr0 = sb + SM_W2
        + (uint32_t)((((lane >> 4) << 3) + (lane & 7)) * PITCH_B
                   + ((lane >> 3) & 1) * 16);

    for (int cid = blockIdx.x * 8 + wid; cid < NCHUNK; cid += NWARPS) {
        const int i  = cid >> 4;
        const int j0 = (cid & 15) * TJW;

        const float2 xi = *(const float2*)(inp + 2 * i);

        // y for warp's 32 j's: lane l owns j0+l
        float y_own;
        {
            float2 qo = *(const float2*)(qxs + 2 * (j0 + lane));
            y_own = sinf(epi * qo.x) * sinf(epi * qo.y);
        }

        float p0 = 0.f, p1 = 0.f, p2 = 0.f, p3 = 0.f;

        #pragma unroll
        for (int mf = 0; mf < 2; mf++) {
            // this half's two fragment rows: j0 + r + 16*mf (+8)
            const float2 qA = *(const float2*)(qxs + 2 * (j0 + r + 16 * mf));
            const float2 qB = *(const float2*)(qxs + 2 * (j0 + r + 16 * mf + 8));

            // ---- A fragments for m16 x k128, computed in registers ----
            uint32_t ah[8][4];
            #pragma unroll
            for (int ks = 0; ks < 8; ks++) {
                const int c0 = ks * 16 + cq;
                float4 ca = cf4s[c0],     cb = cf4s[c0 + 1];
                float4 cc = cf4s[c0 + 8], cd = cf4s[c0 + 9];
                float2 wd01 = *(const float2*)(wds + c0);
                float2 wd89 = *(const float2*)(wds + c0 + 8);
                float ba = fmaf(xi.y, ca.y, fmaf(xi.x, ca.x, ca.z));
                float bb2 = fmaf(xi.y, cb.y, fmaf(xi.x, cb.x, cb.z));
                float bc = fmaf(xi.y, cc.y, fmaf(xi.x, cc.x, cc.z));
                float bd = fmaf(xi.y, cd.y, fmaf(xi.x, cd.x, cd.z));
                float vA0 = fmaf(qA.y, wd01.x, fmaf(qA.x, ca.w, ba));
                float vA1 = fmaf(qA.y, wd01.y, fmaf(qA.x, cb.w, bb2));
                float vA8 = fmaf(qA.y, wd89.x, fmaf(qA.x, cc.w, bc));
                float vA9 = fmaf(qA.y, wd89.y, fmaf(qA.x, cd.w, bd));
                float vB0 = fmaf(qB.y, wd01.x, fmaf(qB.x, ca.w, ba));
                float vB1 = fmaf(qB.y, wd01.y, fmaf(qB.x, cb.w, bb2));
                float vB8 = fmaf(qB.y, wd89.x, fmaf(qB.x, cc.w, bc));
                float vB9 = fmaf(qB.y, wd89.y, fmaf(qB.x, cd.w, bd));
                ah[ks][0] = tanh_a16x2(h2u(__floats2half2_rn(vA0, vA1)));
                ah[ks][1] = tanh_a16x2(h2u(__floats2half2_rn(vB0, vB1)));
                ah[ks][2] = tanh_a16x2(h2u(__floats2half2_rn(vA8, vA9)));
                ah[ks][3] = tanh_a16x2(h2u(__floats2half2_rn(vB8, vB9)));
            }

            // ---- GEMM + fused per-n-block epilogue for this m16 half ----
            #pragma unroll
            for (int nb = 0; nb < 4; nb++) {
                float acc[4][4];
                #pragma unroll
                for (int nf = 0; nf < 4; nf++)
                    #pragma unroll
                    for (int q = 0; q < 4; q++) acc[nf][q] = 0.0f;

                #pragma unroll
                for (int ks = 0; ks < 8; ks++) {
                    uint32_t bh[4][2];
                    uint32_t bA = bAddr0
                        + (uint32_t)(nb * 32 * PITCH_B + ks * 32);
                    ldsm4(bh[0][0], bh[0][1], bh[1][0], bh[1][1], bA);
                    ldsm4(bh[2][0], bh[2][1], bh[3][0], bh[3][1],
                          bA + (uint32_t)(16 * PITCH_B));
                    #pragma unroll
                    for (int nf = 0; nf < 4; nf++)
                        mma_f16(acc[nf], ah[ks], bh[nf]);
                }
                #pragma unroll
                for (int nf = 0; nf < 4; nf++) {
                    const int k = nb * 32 + nf * 8 + cq;
                    float2 c0 = bw[k], c1 = bw[k + 1];
                    float e0 = tanh_a32(acc[nf][0] + c0.x) * c0.y
                             + tanh_a32(acc[nf][1] + c1.x) * c1.y;
                    float e1 = tanh_a32(acc[nf][2] + c0.x) * c0.y
                             + tanh_a32(acc[nf][3] + c1.x) * c1.y;
                    if (mf == 0) { p0 += e0; p1 += e1; }
                    else         { p2 += e0; p3 += e1; }
                }
            }
        }

        // ---- warp reduction: rows r, r+8, r+16, r+24 ----
        p0 += __shfl_xor_sync(0xffffffffu, p0, 1);
        p0 += __shfl_xor_sync(0xffffffffu, p0, 2);
        p1 += __shfl_xor_sync(0xffffffffu, p1, 1);
        p1 += __shfl_xor_sync(0xffffffffu, p1, 2);
        p2 += __shfl_xor_sync(0xffffffffu, p2, 1);
        p2 += __shfl_xor_sync(0xffffffffu, p2, 2);
        p3 += __shfl_xor_sync(0xffffffffu, p3, 1);
        p3 += __shfl_xor_sync(0xffffffffu, p3, 2);
        float s = p0 * __shfl_sync(0xffffffffu, y_own, r)
                + p1 * __shfl_sync(0xffffffffu, y_own, r + 8)
                + p2 * __shfl_sync(0xffffffffu, y_own, r + 16)
                + p3 * __shfl_sync(0xffffffffu, y_own, r + 24);
        if (lane & 3) s = 0.0f;
        #pragma unroll
        for (int o = 16; o > 0; o >>= 1)
            s += __shfl_xor_sync(0xffffffffu, s, o);
        if (lane == 0) g_part[cid] = s;
    }

    // ---- finalize tail: last CTA computes Y and sums g_part -> out ----
    unsigned int* is_last = (unsigned int*)(smem + SM_FLAG);
    __threadfence();                      // publish g_part before ticket
    __syncthreads();
    if (tid == 0)
        *is_last = (atomicAdd(&g_done, 1u) == (unsigned)(NCTA - 1)) ? 1u : 0u;
    __syncthreads();
    if (*is_last) {
        float* yall = (float*)(smem + SM_W2);            // W2 area is dead
        for (int j = tid; j < M_PTS; j += 256) {
            float2 q = *(const float2*)(qxs + 2 * j);
            yall[j] = sinf(epi * q.x) * sinf(epi * q.y);
        }
        __syncthreads();
        if (tid < 16) {
            float p = 0.0f;
            #pragma unroll
            for (int k = 0; k < 32; k++) p += yall[tid * 32 + k];
            yall[M_PTS + tid] = p;
        }
        __syncthreads();
        if (tid == 0) {
            float Y = 0.0f;
            #pragma unroll
            for (int k = 0; k < 16; k++) Y += yall[M_PTS + k];
            yall[M_PTS + 16] = b3[0] * Y;
        }
        __syncthreads();
        const float basev = yall[M_PTS + 16];
        for (int i = tid; i < N_PTS; i += 256) {
            float s2 = basev;
            #pragma unroll
            for (int t = 0; t < JTW; t++) s2 += g_part[i * JTW + t];
            out[i] = s2;
        }
        if (tid == 0) g_done = 0;         // reset: deterministic graph replays
    }
}

// ---------------------------------------------------------------------------
extern "C" void kernel_launch(void* const* d_in, const int* in_sizes, int n_in,
                              void* d_out, int out_size) {
    const float* inp = (const float*)d_in[0];   // [2048, 2]
    const float* qx  = (const float*)d_in[1];   // [512, 2]
    const float* ep  = (const float*)d_in[2];   // [1]
    const float* W1  = (const float*)d_in[3];   // [4, 128]
    const float* b1  = (const float*)d_in[4];   // [128]
    const float* W2  = (const float*)d_in[5];   // [128, 128]
    const float* b2  = (const float*)d_in[6];   // [128]
    const float* W3  = (const float*)d_in[7];   // [128, 1]
    const float* b3  = (const float*)d_in[8];   // [1]
    float* out = (float*)d_out;                 // [2048, 1]
    (void)in_sizes; (void)n_in; (void)out_size;

    cudaFuncSetAttribute(modnet_mma_kernel,
                         cudaFuncAttributeMaxDynamicSharedMemorySize, SMEM_TOTAL);

    modnet_mma_kernel<<<NCTA, 256, SMEM_TOTAL>>>(inp, qx, ep, W1, b1,
                                                 W2, b2, W3, b3, out);
}

// round 16
// speedup vs baseline: 7.2690x; 7.2690x over previous
#include <cuda_runtime.h>
#include <cuda_fp16.h>
#include <stdint.h>
#include <string.h>

#define N_PTS 2048
#define M_PTS 512
#define HID   128
#define TJW   32                  // j's per warp-chunk
#define JTW   16                  // warp-chunks per i
#define NCHUNK (N_PTS * JTW)      // 32768
#define NCTA  296                 // 2 per SM
#define NWARPS (NCTA * 8)
#define PI_F  3.14159265358979323846f

// smem pitch: 136 fp16 per row = 272 B = 17 x 16B -> ldmatrix conflict-free
#define PITCH_B 272
#define H1W_B  (TJW * PITCH_B)    // 8704 per warp

// ---- shared memory layout (bytes) ----
#define SM_W2    0                // [128][136] fp16 (W2^T) 34816
#define SM_H1    34816            // 8 warps x 8704 = 69632
#define SM_B2W3  104448           // 128 x float2 (b2, W3)
#define SM_QX    105472           // 512 x float2 = 4096
#define SM_W1    109568           // 5 x 128 floats = 2560
#define SM_FLAG  112128           // is_last flag (64 B pad)
#define SM_Y     112192           // 512 floats (quadrature weights)
#define SMEM_TOTAL 114240

// ---- device scratch ----
__device__ __align__(16) float g_part[NCHUNK];
__device__ unsigned int g_done;                    // zero-init; reset each run

// ---------------------------------------------------------------------------
__device__ __forceinline__ float tanh_a32(float x) {
    float r;
    asm("tanh.approx.f32 %0, %1;" : "=f"(r) : "f"(x));
    return r;
}
__device__ __forceinline__ uint32_t tanh_a16x2(uint32_t x2) {
    uint32_t r;
    asm("tanh.approx.f16x2 %0, %1;" : "=r"(r) : "r"(x2));
    return r;
}
__device__ __forceinline__ uint32_t smem_u32(const void* p) {
    uint32_t a;
    asm("{ .reg .u64 t; cvta.to.shared.u64 t, %1; cvt.u32.u64 %0, t; }"
        : "=r"(a) : "l"(p));
    return a;
}
__device__ __forceinline__ void ldsm4(uint32_t& r0, uint32_t& r1,
                                      uint32_t& r2, uint32_t& r3, uint32_t addr) {
    asm volatile("ldmatrix.sync.aligned.m8n8.x4.shared.b16 {%0,%1,%2,%3}, [%4];"
                 : "=r"(r0), "=r"(r1), "=r"(r2), "=r"(r3) : "r"(addr));
}
__device__ __forceinline__ void mma_f16(float* d, const uint32_t* a,
                                        const uint32_t* b) {
    asm volatile(
        "mma.sync.aligned.m16n8k16.row.col.f32.f16.f16.f32 "
        "{%0,%1,%2,%3}, {%4,%5,%6,%7}, {%8,%9}, {%0,%1,%2,%3};"
        : "+f"(d[0]), "+f"(d[1]), "+f"(d[2]), "+f"(d[3])
        : "r"(a[0]), "r"(a[1]), "r"(a[2]), "r"(a[3]), "r"(b[0]), "r"(b[1]));
}
__device__ __forceinline__ uint32_t h2u(__half2 h) {
    uint32_t u; memcpy(&u, &h, 4); return u;
}

// ---------------------------------------------------------------------------
// Single persistent kernel, warp-autonomous chunks (R13 structure).
// 256 threads = 8 warps, 2 CTAs/SM. Warp-chunk = (i, 32 j's).
// y[512] precomputed to smem ONCE in the prologue (no sinf in main loop).
//   Phase 1: layer-1 inline + tanh.approx.f16x2 -> warp-private h1 strip.
//   A-frags (m32 x k128) register-resident via 16 ldsm.x4.
//   GEMM: 4 n-blocks of 32; per nb: 8 ks x (2 B-ldsm + 8 HMMA), then fused
//         epilogue tanh.approx.f32 + W3 dot into 4 row-partials.
//   Warp shfl reduction, y from smem, 1 STG per chunk -> g_part.
// Tail: last CTA (atomic ticket) sums y (fixed order) and g_part -> out.
// ---------------------------------------------------------------------------
__global__ void __launch_bounds__(256, 2) modnet_mma_kernel(
        const float* __restrict__ inp,
        const float* __restrict__ qx,
        const float* __restrict__ ep,
        const float* __restrict__ W1,
        const float* __restrict__ b1,
        const float* __restrict__ W2,
        const float* __restrict__ b2,
        const float* __restrict__ W3,
        const float* __restrict__ b3,
        float* __restrict__ out) {
    extern __shared__ char smem[];
    const uint32_t sb = smem_u32(smem);
    const int tid = threadIdx.x, lane = tid & 31, wid = tid >> 5;

    // ---- prologue: W2^T (fp16), b2/W3, W1/b1, qx, y into smem ----
    for (int e = tid; e < HID * 64; e += 256) {
        int n = e & 127, cp = e >> 7, c = cp * 2;
        __half2 h = __floats2half2_rn(W2[c * HID + n], W2[(c + 1) * HID + n]);
        *(uint32_t*)(smem + SM_W2 + (uint32_t)(n * PITCH_B + cp * 4)) = h2u(h);
    }
    if (tid < HID) {
        float2 v; v.x = b2[tid]; v.y = W3[tid];
        *(float2*)(smem + SM_B2W3 + tid * 8) = v;
        float* w1s = (float*)(smem + SM_W1);
        w1s[tid]       = W1[tid];
        w1s[128 + tid] = W1[128 + tid];
        w1s[256 + tid] = W1[256 + tid];
        w1s[384 + tid] = W1[384 + tid];
        w1s[512 + tid] = b1[tid];
    }
    for (int e = tid; e < M_PTS * 2; e += 256)
        ((float*)(smem + SM_QX))[e] = qx[e];
    {
        const float epi0 = ep[0] * PI_F;
        for (int j = tid; j < M_PTS; j += 256) {
            float qa = qx[2 * j], qb = qx[2 * j + 1];
            ((float*)(smem + SM_Y))[j] = sinf(epi0 * qa) * sinf(epi0 * qb);
        }
    }
    __syncthreads();

    const float2* bw  = (const float2*)(smem + SM_B2W3);
    const float*  qxs = (const float*)(smem + SM_QX);
    const float*  w1s = (const float*)(smem + SM_W1);
    const float*  ysm = (const float*)(smem + SM_Y);
    const int c4 = lane * 4;

    // warp-private h1 strip + lane-invariant ldsm addressing
    const uint32_t hbase = sb + SM_H1 + (uint32_t)(wid * H1W_B);
    const uint32_t aAddr0 = hbase + (uint32_t)((lane & 15) * PITCH_B
                                             + (lane >> 4) * 16);
    const uint32_t bAddr0 = sb + SM_W2
        + (uint32_t)((((lane >> 4) << 3) + (lane & 7)) * PITCH_B
                   + ((lane >> 3) & 1) * 16);

    for (int cid = blockIdx.x * 8 + wid; cid < NCHUNK; cid += NWARPS) {
        const int i  = cid >> 4;
        const int j0 = (cid & 15) * TJW;

        __syncwarp();    // prior chunk's ldsm reads done before overwrite

        // ---- phase 1: h1 = tanh(layer1) -> warp-private strip ----
        const float4 wcc = *(const float4*)(w1s + 256 + c4);
        const float4 wdd = *(const float4*)(w1s + 384 + c4);
        float4 base;
        {
            const float4 w0  = *(const float4*)(w1s + c4);
            const float4 w1r = *(const float4*)(w1s + 128 + c4);
            const float4 bb  = *(const float4*)(w1s + 512 + c4);
            const float2 xi  = *(const float2*)(inp + 2 * i);
            base.x = xi.x * w0.x + xi.y * w1r.x + bb.x;
            base.y = xi.x * w0.y + xi.y * w1r.y + bb.y;
            base.z = xi.x * w0.z + xi.y * w1r.z + bb.z;
            base.w = xi.x * w0.w + xi.y * w1r.w + bb.w;
        }
        #pragma unroll 8
        for (int it = 0; it < TJW; it++) {
            float2 q = *(const float2*)(qxs + 2 * (j0 + it));
            float a0 = base.x + q.x * wcc.x + q.y * wdd.x;
            float a1 = base.y + q.x * wcc.y + q.y * wdd.y;
            float a2 = base.z + q.x * wcc.z + q.y * wdd.z;
            float a3 = base.w + q.x * wcc.w + q.y * wdd.w;
            uint32_t t01 = tanh_a16x2(h2u(__floats2half2_rn(a0, a1)));
            uint32_t t23 = tanh_a16x2(h2u(__floats2half2_rn(a2, a3)));
            *(uint2*)(smem + (SM_H1 + wid * H1W_B) + it * PITCH_B + lane * 8)
                = make_uint2(t01, t23);
        }
        // y for this warp's 32 j's: lane l owns j0+l (precomputed smem)
        const float y_own = ysm[j0 + lane];
        __syncwarp();

        // ---- A fragments: m32 x k128, register-resident ----
        uint32_t ah[2][8][4];
        #pragma unroll
        for (int mf = 0; mf < 2; mf++)
            #pragma unroll
            for (int ks = 0; ks < 8; ks++)
                ldsm4(ah[mf][ks][0], ah[mf][ks][1], ah[mf][ks][2], ah[mf][ks][3],
                      aAddr0 + (uint32_t)(mf * 16 * PITCH_B + ks * 32));

        // ---- GEMM + fused per-n-block epilogue ----
        const int q2 = (lane & 3) * 2;
        float p0 = 0.f, p1 = 0.f, p2 = 0.f, p3 = 0.f;
        #pragma unroll
        for (int nb = 0; nb < 4; nb++) {
            float acc[2][4][4];
            #pragma unroll
            for (int mf = 0; mf < 2; mf++)
                #pragma unroll
                for (int nf = 0; nf < 4; nf++)
                    #pragma unroll
                    for (int q = 0; q < 4; q++) acc[mf][nf][q] = 0.0f;

            #pragma unroll
            for (int ks = 0; ks < 8; ks++) {
                uint32_t bh[4][2];
                uint32_t bA = bAddr0 + (uint32_t)(nb * 32 * PITCH_B + ks * 32);
                ldsm4(bh[0][0], bh[0][1], bh[1][0], bh[1][1], bA);
                ldsm4(bh[2][0], bh[2][1], bh[3][0], bh[3][1],
                      bA + (uint32_t)(16 * PITCH_B));
                #pragma unroll
                for (int mf = 0; mf < 2; mf++)
                    #pragma unroll
                    for (int nf = 0; nf < 4; nf++)
                        mma_f16(acc[mf][nf], ah[mf][ks], bh[nf]);
            }
            #pragma unroll
            for (int mf = 0; mf < 2; mf++)
                #pragma unroll
                for (int nf = 0; nf < 4; nf++) {
                    const int k = nb * 32 + nf * 8 + q2;
                    float2 c0 = bw[k], c1 = bw[k + 1];
                    float e0 = tanh_a32(acc[mf][nf][0] + c0.x) * c0.y
                             + tanh_a32(acc[mf][nf][1] + c1.x) * c1.y;
                    float e1 = tanh_a32(acc[mf][nf][2] + c0.x) * c0.y
                             + tanh_a32(acc[mf][nf][3] + c1.x) * c1.y;
                    if (mf == 0) { p0 += e0; p1 += e1; }
                    else         { p2 += e0; p3 += e1; }
                }
        }

        // ---- warp reduction: rows r, r+8, r+16, r+24 (r = lane>>2) ----
        p0 += __shfl_xor_sync(0xffffffffu, p0, 1);
        p0 += __shfl_xor_sync(0xffffffffu, p0, 2);
        p1 += __shfl_xor_sync(0xffffffffu, p1, 1);
        p1 += __shfl_xor_sync(0xffffffffu, p1, 2);
        p2 += __shfl_xor_sync(0xffffffffu, p2, 1);
        p2 += __shfl_xor_sync(0xffffffffu, p2, 2);
        p3 += __shfl_xor_sync(0xffffffffu, p3, 1);
        p3 += __shfl_xor_sync(0xffffffffu, p3, 2);
        const int r = lane >> 2;
        float s = p0 * __shfl_sync(0xffffffffu, y_own, r)
                + p1 * __shfl_sync(0xffffffffu, y_own, r + 8)
                + p2 * __shfl_sync(0xffffffffu, y_own, r + 16)
                + p3 * __shfl_sync(0xffffffffu, y_own, r + 24);
        if (lane & 3) s = 0.0f;
        #pragma unroll
        for (int o = 16; o > 0; o >>= 1)
            s += __shfl_xor_sync(0xffffffffu, s, o);
        if (lane == 0) g_part[cid] = s;
    }

    // ---- finalize tail: last CTA sums Y (fixed order) and g_part -> out ----
    unsigned int* is_last = (unsigned int*)(smem + SM_FLAG);
    __threadfence();                      // publish g_part before ticket
    __syncthreads();
    if (tid == 0)
        *is_last = (atomicAdd(&g_done, 1u) == (unsigned)(NCTA - 1)) ? 1u : 0u;
    __syncthreads();
    if (*is_last) {
        float* tmp = (float*)(smem + SM_H1);             // h1 area is dead
        if (tid < 16) {
            float p = 0.0f;
            #pragma unroll
            for (int k = 0; k < 32; k++) p += ysm[tid * 32 + k];
            tmp[tid] = p;
        }
        __syncthreads();
        if (tid == 0) {
            float Y = 0.0f;
            #pragma unroll
            for (int k = 0; k < 16; k++) Y += tmp[k];
            tmp[16] = b3[0] * Y;
        }
        __syncthreads();
        const float basev = tmp[16];
        for (int i = tid; i < N_PTS; i += 256) {
            float s2 = basev;
            #pragma unroll
            for (int t = 0; t < JTW; t++) s2 += g_part[i * JTW + t];
            out[i] = s2;
        }
        if (tid == 0) g_done = 0;         // reset: deterministic graph replays
    }
}

// ---------------------------------------------------------------------------
extern "C" void kernel_launch(void* const* d_in, const int* in_sizes, int n_in,
                              void* d_out, int out_size) {
    const float* inp = (const float*)d_in[0];   // [2048, 2]
    const float* qx  = (const float*)d_in[1];   // [512, 2]
    const float* ep  = (const float*)d_in[2];   // [1]
    const float* W1  = (const float*)d_in[3];   // [4, 128]
    const float* b1  = (const float*)d_in[4];   // [128]
    const float* W2  = (const float*)d_in[5];   // [128, 128]
    const float* b2  = (const float*)d_in[6];   // [128]
    const float* W3  = (const float*)d_in[7];   // [128, 1]
    const float* b3  = (const float*)d_in[8];   // [1]
    float* out = (float*)d_out;                 // [2048, 1]
    (void)in_sizes; (void)n_in; (void)out_size;

    cudaFuncSetAttribute(modnet_mma_kernel,
                         cudaFuncAttributeMaxDynamicSharedMemorySize, SMEM_TOTAL);

    modnet_mma_kernel<<<NCTA, 256, SMEM_TOTAL>>>(inp, qx, ep, W1, b1,
                                                 W2, b2, W3, b3, out);
}